// round 1
// baseline (speedup 1.0000x reference)
#include <cuda_runtime.h>
#include <cuda_bf16.h>

// Problem constants (from reference):
//   x:       (L=2048, B=16) int32 token ids, row-major -> x[l*B + b]
//   embed_w: (V=50257, D=1024) fp32           -> w[t*D + d]
//   out:     (B=16, D=1024, L=2048) fp32      -> out[b*D*L + d*L + l]
//   rows >= MAX_TOKEN_SIZE(20) are zeroed; output scaled by sqrt(8).

#define L_DIM   2048
#define B_DIM   16
#define D_DIM   1024
#define MAXTOK  20
#define SCALE   2.8284271247461903f  // sqrt(8)

// total output floats = 16*1024*2048 = 33,554,432 ; /4 = 8,388,608 float4
#define TOTAL4  8388608

__global__ void __launch_bounds__(256) embed_gather_kernel(
    const int* __restrict__ x,
    const float* __restrict__ w,
    float4* __restrict__ out)
{
    int i4 = blockIdx.x * blockDim.x + threadIdx.x;
    if (i4 >= TOTAL4) return;

    // i4 layout: [b][d][l4], l4 = l/4 innermost (512 per (b,d))
    int l4   = i4 & 511;          // L/4 = 512
    int rest = i4 >> 9;
    int d    = rest & (D_DIM - 1);
    int b    = rest >> 10;
    int l    = l4 << 2;

    // 4 token ids for consecutive l (same b). x is 128 KiB -> L1/L2 resident.
    int base = l * B_DIM + b;
    int t0 = __ldg(x + base);
    int t1 = __ldg(x + base + B_DIM);
    int t2 = __ldg(x + base + 2 * B_DIM);
    int t3 = __ldg(x + base + 3 * B_DIM);

    float4 v;
    v.x = (t0 < MAXTOK) ? __ldg(w + (size_t)t0 * D_DIM + d) * SCALE : 0.0f;
    v.y = (t1 < MAXTOK) ? __ldg(w + (size_t)t1 * D_DIM + d) * SCALE : 0.0f;
    v.z = (t2 < MAXTOK) ? __ldg(w + (size_t)t2 * D_DIM + d) * SCALE : 0.0f;
    v.w = (t3 < MAXTOK) ? __ldg(w + (size_t)t3 * D_DIM + d) * SCALE : 0.0f;

    // Streaming store: output (128 MiB) would thrash L2; keep x hot instead.
    __stcs(out + i4, v);
}

extern "C" void kernel_launch(void* const* d_in, const int* in_sizes, int n_in,
                              void* d_out, int out_size)
{
    const int*   x = (const int*)d_in[0];    // (L, B) int32
    const float* w = (const float*)d_in[1];  // (V, D) fp32
    float4*      o = (float4*)d_out;         // (B, D, L) fp32

    const int threads = 256;
    const int blocks  = TOTAL4 / threads;    // 32768
    embed_gather_kernel<<<blocks, threads>>>(x, w, o);
}

// round 2
// speedup vs baseline: 4.5795x; 4.5795x over previous
#include <cuda_runtime.h>
#include <cuda_bf16.h>

// x:       (L=2048, B=16) int32   -> x[l*16 + b]
// embed_w: (V=50257, D=1024) fp32 -> w[t*1024 + d]
// out:     (B=16, D=1024, L=2048) fp32 -> out[b*D*L + d*L + l]
// rows with token >= 20 are zero; output scaled by sqrt(8).

#define L_DIM   2048
#define B_DIM   16
#define D_DIM   1024
#define MAXTOK  20
#define SCALE   2.8284271247461903f  // sqrt(8)

#define TOTAL4  8388608   // 16*1024*2048 / 4  float4 elements
#define NPOS    32768     // L*B token positions

// ---------------------------------------------------------------------------
// Kernel 1: zero-fill output. Pure streaming stores, no loads.
// 4096 blocks x 256 threads x 8 float4 each, fully coalesced strided layout.
// ---------------------------------------------------------------------------
#define ZBLOCKS 4096
#define ZTPB    256
#define ZITER   8   // 4096*256*8 = 8388608

__global__ void __launch_bounds__(ZTPB) zero_fill_kernel(float4* __restrict__ out)
{
    const float4 z = make_float4(0.f, 0.f, 0.f, 0.f);
    unsigned idx = blockIdx.x * ZTPB + threadIdx.x;
    const unsigned stride = ZBLOCKS * ZTPB;  // 1048576
    #pragma unroll
    for (int k = 0; k < ZITER; k++) {
        __stcs(out + idx, z);
        idx += stride;
    }
}

// ---------------------------------------------------------------------------
// Kernel 2: scatter the rare nonzero rows. One warp per (l,b) position.
// Almost every warp exits after one (L2-resident) token load.
// ---------------------------------------------------------------------------
#define SWARPS_PER_BLOCK 8
#define SBLOCKS (NPOS / SWARPS_PER_BLOCK)   // 4096

__global__ void __launch_bounds__(SWARPS_PER_BLOCK * 32) scatter_kernel(
    const int* __restrict__ x,
    const float* __restrict__ w,
    float* __restrict__ out)
{
    int warp = threadIdx.x >> 5;
    int lane = threadIdx.x & 31;
    int pos  = blockIdx.x * SWARPS_PER_BLOCK + warp;   // 0..32767

    int t = 0;
    if (lane == 0) t = __ldg(x + pos);
    t = __shfl_sync(0xFFFFFFFFu, t, 0);
    if (t >= MAXTOK) return;                 // ~99.96% of warps exit here

    int l = pos >> 4;          // pos = l*16 + b
    int b = pos & 15;

    const float* wrow = w + (size_t)t * D_DIM;
    float* obase = out + ((size_t)b * D_DIM * L_DIM) + l;

    #pragma unroll 8
    for (int d = lane; d < D_DIM; d += 32) {
        obase[(size_t)d * L_DIM] = __ldg(wrow + d) * SCALE;
    }
}

// ---------------------------------------------------------------------------
extern "C" void kernel_launch(void* const* d_in, const int* in_sizes, int n_in,
                              void* d_out, int out_size)
{
    const int*   x = (const int*)d_in[0];
    const float* w = (const float*)d_in[1];

    zero_fill_kernel<<<ZBLOCKS, ZTPB>>>((float4*)d_out);
    scatter_kernel<<<SBLOCKS, SWARPS_PER_BLOCK * 32>>>(x, w, (float*)d_out);
}